// round 5
// baseline (speedup 1.0000x reference)
#include <cuda_runtime.h>

// ---------------------------------------------------------------------------
// SymplecticLeapfrogLayer: fused 3-step leapfrog integrator of a Hamiltonian
// MLP (256->256->256->1, tanh) over B=65536 independent states of dim 256.
//
// Strategy: one CTA owns 64 batch rows. State S=[q|p] (64x256 f32), H1 and G
// activation buffers all live in shared memory for the whole kernel. Each dH
// evaluation = 4 GEMMs (64x256x256) with weight panels streamed from L2 into
// a double-buffered 2x16x256 SMEM staging area. Inner loop uses packed
// fma.rn.f32x2 (FFMA2) for 2x fp32 throughput.
// ---------------------------------------------------------------------------

#define DT_STEP 0.1f
#define FDIM 128
#define NF 256

typedef unsigned long long u64;

// Pre-transposed weights (filled by transpose_weights each launch)
__device__ float g_W1T[NF * NF];
__device__ float g_W2T[NF * NF];

__device__ __forceinline__ u64 pack_dup(float x) {
    u64 r; asm("mov.b64 %0, {%1, %1};" : "=l"(r) : "f"(x)); return r;
}
__device__ __forceinline__ void fma2(u64& d, u64 a, u64 b) {
    asm("fma.rn.f32x2 %0, %1, %2, %3;" : "=l"(d) : "l"(a), "l"(b), "l"(d));
}
__device__ __forceinline__ float2 unpk(u64 v) {
    float2 f; asm("mov.b64 {%0, %1}, %2;" : "=f"(f.x), "=f"(f.y) : "l"(v)); return f;
}
__device__ __forceinline__ float fast_tanh(float x) {
    float r; asm("tanh.approx.f32 %0, %1;" : "=f"(r) : "f"(x)); return r;
}

// SMEM layout in floats
#define SM_S   0        // state [64][256]
#define SM_H1  16384    // h1 / g1 [64][256]
#define SM_G   32768    // g2 [64][256]
#define SM_W   49152    // weight panels: 2 x (16 x 256)
#define SMEM_BYTES ((49152 + 8192) * 4)   // 229376 B

// ---------------------------------------------------------------------------
__global__ void transpose_weights(const float* __restrict__ W1,
                                  const float* __restrict__ W2) {
    __shared__ float tile[32][33];
    const float* src = blockIdx.z ? W2 : W1;
    float* dst       = blockIdx.z ? g_W2T : g_W1T;
    int x = blockIdx.x * 32 + threadIdx.x;
    int y = blockIdx.y * 32 + threadIdx.y;
#pragma unroll
    for (int i = 0; i < 32; i += 8)
        tile[threadIdx.y + i][threadIdx.x] = src[(y + i) * NF + x];
    __syncthreads();
    x = blockIdx.y * 32 + threadIdx.x;
    y = blockIdx.x * 32 + threadIdx.y;
#pragma unroll
    for (int i = 0; i < 32; i += 8)
        dst[(y + i) * NF + x] = tile[threadIdx.x][threadIdx.y + i];
}

// ---------------------------------------------------------------------------
// One 64x256x256 GEMM: Out[r][c] = sum_k A[r][k] * Wg[k][c], plus epilogue.
// Thread map: tx=tid&15, ty=tid>>4. Thread owns rows ty*4+{0..3},
// columns 4*tx + 64*jj + {0..3} for jj < NJJ.
//
// EPI 0: H1 = tanh(acc + b1)
// EPI 1: G  = Wout * (1 - tanh(acc + b2)^2)          (g2)
// EPI 2: H1 = acc * (1 - H1^2)                       (g1, RMW on H1)
// EPI 3: full leapfrog update of S from dH=acc
// EPI 4: p-only update of S (NJJ=2 -> columns < 128 only)
// ---------------------------------------------------------------------------
template <int NJJ, int EPI>
__device__ __forceinline__ void gemm_tile(
    float* sm, int aOff,
    const float* __restrict__ Wg,
    const float* __restrict__ bias,
    const float* __restrict__ wout,
    float coefQ, float coefP, int tid)
{
    const int tx = tid & 15, ty = tid >> 4;

    u64 acc[4][2 * NJJ];
#pragma unroll
    for (int i = 0; i < 4; i++)
#pragma unroll
        for (int j = 0; j < 2 * NJJ; j++) acc[i][j] = 0ull;

    float* wbuf = sm + SM_W;
    const float4* wg4 = reinterpret_cast<const float4*>(Wg);
    const float* A = sm + aOff;

    // prefetch + stage panel 0
    float4 r0 = wg4[tid], r1 = wg4[tid + 256], r2 = wg4[tid + 512], r3 = wg4[tid + 768];
    __syncthreads();   // previous GEMM's compute/epilogue fully done
    {
        float4* wb4 = reinterpret_cast<float4*>(wbuf);
        wb4[tid] = r0; wb4[tid + 256] = r1; wb4[tid + 512] = r2; wb4[tid + 768] = r3;
    }

#pragma unroll 1
    for (int pan = 0; pan < 16; ++pan) {
        __syncthreads();                    // panel pan staged for everyone
        if (pan < 15) {                     // prefetch next panel (overlaps compute)
            const float4* srcp = wg4 + (pan + 1) * 1024;
            r0 = srcp[tid]; r1 = srcp[tid + 256];
            r2 = srcp[tid + 512]; r3 = srcp[tid + 768];
        }
        const float* wp = wbuf + (pan & 1) * 4096;
#pragma unroll
        for (int kk = 0; kk < 16; kk += 4) {
            float4 a4[4];
#pragma unroll
            for (int i = 0; i < 4; i++)
                a4[i] = *reinterpret_cast<const float4*>(A + (ty * 4 + i) * NF + pan * 16 + kk);
#pragma unroll
            for (int dk = 0; dk < 4; ++dk) {
                u64 ap[4];
#pragma unroll
                for (int i = 0; i < 4; i++) {
                    float av = dk == 0 ? a4[i].x : dk == 1 ? a4[i].y : dk == 2 ? a4[i].z : a4[i].w;
                    ap[i] = pack_dup(av);
                }
                const float* wr = wp + (kk + dk) * NF;
#pragma unroll
                for (int jj = 0; jj < NJJ; jj++) {
                    ulonglong2 bv = *reinterpret_cast<const ulonglong2*>(wr + 4 * tx + 64 * jj);
#pragma unroll
                    for (int i = 0; i < 4; i++) {
                        fma2(acc[i][2 * jj + 0], ap[i], bv.x);
                        fma2(acc[i][2 * jj + 1], ap[i], bv.y);
                    }
                }
            }
        }
        if (pan < 15) {  // stage next panel into the other buffer (safe: all threads
                         // passed top-of-iter sync, so nobody still reads it)
            float4* wb4 = reinterpret_cast<float4*>(wbuf + ((pan + 1) & 1) * 4096);
            wb4[tid] = r0; wb4[tid + 256] = r1; wb4[tid + 512] = r2; wb4[tid + 768] = r3;
        }
    }

    // epilogue — each thread touches only elements it owns
#pragma unroll
    for (int i = 0; i < 4; i++) {
        int rr = ty * 4 + i;
#pragma unroll
        for (int jj = 0; jj < NJJ; jj++) {
            float2 v0 = unpk(acc[i][2 * jj + 0]);
            float2 v1 = unpk(acc[i][2 * jj + 1]);
            float vals[4] = {v0.x, v0.y, v1.x, v1.y};
            int c0 = 4 * tx + 64 * jj;
#pragma unroll
            for (int e = 0; e < 4; e++) {
                int c = c0 + e;
                float v = vals[e];
                if (EPI == 0) {
                    float h = fast_tanh(v + __ldg(bias + c));
                    sm[SM_H1 + rr * NF + c] = h;
                } else if (EPI == 1) {
                    float h = fast_tanh(v + __ldg(bias + c));
                    sm[SM_G + rr * NF + c] = __ldg(wout + c) * (1.0f - h * h);
                } else if (EPI == 2) {
                    float h1 = sm[SM_H1 + rr * NF + c];
                    sm[SM_H1 + rr * NF + c] = v * (1.0f - h1 * h1);
                } else if (EPI == 3) {
                    if (jj < 2) sm[SM_S + rr * NF + FDIM + c] -= coefP * v;   // p += 0.5*DT*(-dH_q)
                    else        sm[SM_S + rr * NF + (c - FDIM)] += coefQ * v; // q += DT*dH_p
                } else {  // EPI 4 (NJJ==2, all c < 128)
                    sm[SM_S + rr * NF + FDIM + c] -= coefP * v;
                }
            }
        }
    }
}

// ---------------------------------------------------------------------------
__global__ void __launch_bounds__(256, 1) leapfrog_kernel(
    const float* __restrict__ x,
    const float* __restrict__ W1, const float* __restrict__ b1,
    const float* __restrict__ W2, const float* __restrict__ b2,
    const float* __restrict__ Wout,
    float* __restrict__ out)
{
    extern __shared__ float sm[];
    const int tid = threadIdx.x;
    const int rowBase = blockIdx.x * 64;

    // Load S = [q | p]: q = x[b,15,:], p = x[b,15,:] - x[b,14,:]
    const float4* x4 = reinterpret_cast<const float4*>(x);
#pragma unroll
    for (int it = 0; it < 8; ++it) {
        int f4 = tid + it * 256;        // 0..2047
        int row = f4 >> 5;              // 0..63
        int fc = f4 & 31;               // float4 index within 128 floats
        int b = rowBase + row;
        float4 q = x4[(b * 16 + 15) * 32 + fc];
        float4 xm = x4[(b * 16 + 14) * 32 + fc];
        float4 p = make_float4(q.x - xm.x, q.y - xm.y, q.z - xm.z, q.w - xm.w);
        *reinterpret_cast<float4*>(sm + SM_S + row * NF + fc * 4) = q;
        *reinterpret_cast<float4*>(sm + SM_S + row * NF + FDIM + fc * 4) = p;
    }
    // (first gemm_tile's entry __syncthreads orders these writes before A reads)

#pragma unroll 1
    for (int step = 0; step < 3; ++step) {
        // eval 1: dH at (q,p); p += 0.5*DT*dp, q += DT*dq
        gemm_tile<4, 0>(sm, SM_S,  W1,    b1, nullptr, 0.f, 0.f, tid);
        gemm_tile<4, 1>(sm, SM_H1, W2,    b2, Wout,    0.f, 0.f, tid);
        gemm_tile<4, 2>(sm, SM_G,  g_W2T, nullptr, nullptr, 0.f, 0.f, tid);
        gemm_tile<4, 3>(sm, SM_H1, g_W1T, nullptr, nullptr, DT_STEP, 0.5f * DT_STEP, tid);
        // eval 2: dH2 at updated (q,p); p += 0.5*DT*(-dH2_q) — only cols<128 needed
        gemm_tile<4, 0>(sm, SM_S,  W1,    b1, nullptr, 0.f, 0.f, tid);
        gemm_tile<4, 1>(sm, SM_H1, W2,    b2, Wout,    0.f, 0.f, tid);
        gemm_tile<4, 2>(sm, SM_G,  g_W2T, nullptr, nullptr, 0.f, 0.f, tid);
        gemm_tile<2, 4>(sm, SM_H1, g_W1T, nullptr, nullptr, 0.f, 0.5f * DT_STEP, tid);
    }

    __syncthreads();
    float4* o4 = reinterpret_cast<float4*>(out);
#pragma unroll
    for (int it = 0; it < 16; ++it) {
        int f4 = tid + it * 256;        // 0..4095
        int row = f4 >> 6;              // 64 float4 per output row
        int fc = f4 & 63;
        o4[(rowBase + row) * 64 + fc] =
            *reinterpret_cast<const float4*>(sm + SM_S + row * NF + fc * 4);
    }
}

// ---------------------------------------------------------------------------
extern "C" void kernel_launch(void* const* d_in, const int* in_sizes, int n_in,
                              void* d_out, int out_size) {
    const float* x    = (const float*)d_in[0];
    const float* W1   = (const float*)d_in[1];
    const float* b1   = (const float*)d_in[2];
    const float* W2   = (const float*)d_in[3];
    const float* b2   = (const float*)d_in[4];
    const float* Wout = (const float*)d_in[5];
    float* out = (float*)d_out;

    transpose_weights<<<dim3(8, 8, 2), dim3(32, 8)>>>(W1, W2);

    cudaFuncSetAttribute(leapfrog_kernel,
                         cudaFuncAttributeMaxDynamicSharedMemorySize, SMEM_BYTES);
    leapfrog_kernel<<<1024, 256, SMEM_BYTES>>>(x, W1, b1, W2, b2, Wout, out);
}

// round 14
// speedup vs baseline: 4.2197x; 4.2197x over previous
#include <cuda_runtime.h>
#include <cuda_bf16.h>
#include <cstdint>

// ===========================================================================
// SymplecticLeapfrogLayer via mma.sync bf16 (baseline PTX — the harness
// targets plain sm_103, so tcgen05/'a'-features are unavailable; HMMA is the
// fastest compilable path).
// One CTA = 64 batch rows. S=[q|p] f32 in SMEM for the whole kernel.
// Each dH eval = 4 GEMMs (64x256x256). Per GEMM: warp w owns N-cols
// [32w,32w+32), all 64 M rows -> 16 m16n8k16 accumulators in registers.
// A (bf16 activations) in SMEM via ldmatrix.x4; B (bf16 weights, [N][K]
// K-major) streamed as K=64 SMEM panels via ldmatrix.x2. Epilogues operate
// on register D-fragments directly.
// ===========================================================================

#define NF 256
#define MR 64
#define SSTR 260      // S f32 row stride (floats); 1040B, +16B bank shift/row
#define ASTRB 528     // X/Y bf16 row stride in BYTES (264 bf16)
#define PSTRB 144     // weight panel row stride in BYTES (72 bf16)

// ---- SMEM byte offsets ----------------------------------------------------
#define SMB_S  0
#define SMB_X  (MR * SSTR * 4)            // 66560
#define SMB_Y  (SMB_X + MR * ASTRB)       // 100352
#define SMB_P  (SMB_Y + MR * ASTRB)       // 134144
#define SMB_B1 (SMB_P + 256 * PSTRB)      // 171008
#define SMB_B2 (SMB_B1 + 1024)
#define SMB_WO (SMB_B2 + 1024)
#define SMEM_TOTAL (SMB_WO + 1024)        // 174080 B

// bf16 weights, K-major [N][K] (prepared per launch)
__device__ __nv_bfloat16 g_WB1[NF * NF];    // B[n][k] = W1[k][n]
__device__ __nv_bfloat16 g_WB2[NF * NF];    // B[n][k] = W2[k][n]
__device__ __nv_bfloat16 g_WB2T[NF * NF];   // B[n][k] = W2[n][k]
__device__ __nv_bfloat16 g_WB1T[NF * NF];   // B[n][k] = W1[n][k]

// ---- helpers --------------------------------------------------------------
__device__ __forceinline__ uint32_t smem_u32(const void* p) {
    uint32_t a;
    asm("{ .reg .u64 t; cvta.to.shared.u64 t, %1; cvt.u32.u64 %0, t; }"
        : "=r"(a) : "l"(p));
    return a;
}
__device__ __forceinline__ float lds_f32(uint32_t a) {
    float v; asm volatile("ld.shared.f32 %0, [%1];" : "=f"(v) : "r"(a)); return v;
}
__device__ __forceinline__ void sts_f32(uint32_t a, float v) {
    asm volatile("st.shared.f32 [%0], %1;" :: "r"(a), "f"(v) : "memory");
}
__device__ __forceinline__ uint32_t lds_b32(uint32_t a) {
    uint32_t v; asm volatile("ld.shared.b32 %0, [%1];" : "=r"(v) : "r"(a)); return v;
}
__device__ __forceinline__ void sts_b32(uint32_t a, uint32_t v) {
    asm volatile("st.shared.b32 [%0], %1;" :: "r"(a), "r"(v) : "memory");
}
__device__ __forceinline__ void sts_128(uint32_t a, uint4 v) {
    asm volatile("st.shared.v4.b32 [%0], {%1,%2,%3,%4};"
                 :: "r"(a), "r"(v.x), "r"(v.y), "r"(v.z), "r"(v.w) : "memory");
}
__device__ __forceinline__ float fast_tanh(float x) {
    float r; asm("tanh.approx.f32 %0, %1;" : "=f"(r) : "f"(x)); return r;
}
__device__ __forceinline__ uint32_t pack_bf16x2(float lo, float hi) {
    uint32_t r;
    asm("cvt.rn.bf16x2.f32 %0, %1, %2;" : "=r"(r) : "f"(hi), "f"(lo));
    return r;
}
__device__ __forceinline__ void unpack_bf16x2(uint32_t v, float& f0, float& f1) {
    __nv_bfloat162 h = *reinterpret_cast<__nv_bfloat162*>(&v);
    f0 = __bfloat162float(h.x); f1 = __bfloat162float(h.y);
}
__device__ __forceinline__ void ldm_x4(uint32_t a, uint32_t r[4]) {
    asm volatile("ldmatrix.sync.aligned.m8n8.x4.shared.b16 {%0,%1,%2,%3}, [%4];"
                 : "=r"(r[0]), "=r"(r[1]), "=r"(r[2]), "=r"(r[3]) : "r"(a));
}
__device__ __forceinline__ void ldm_x2(uint32_t a, uint32_t r[2]) {
    asm volatile("ldmatrix.sync.aligned.m8n8.x2.shared.b16 {%0,%1}, [%2];"
                 : "=r"(r[0]), "=r"(r[1]) : "r"(a));
}
__device__ __forceinline__ void mma_bf16(float d[4], const uint32_t a[4], const uint32_t b[2]) {
    asm volatile(
        "mma.sync.aligned.m16n8k16.row.col.f32.bf16.bf16.f32 "
        "{%0,%1,%2,%3},{%4,%5,%6,%7},{%8,%9},{%0,%1,%2,%3};"
        : "+f"(d[0]), "+f"(d[1]), "+f"(d[2]), "+f"(d[3])
        : "r"(a[0]), "r"(a[1]), "r"(a[2]), "r"(a[3]), "r"(b[0]), "r"(b[1]));
}

// ---- weight prep: fp32 -> bf16, K-major [N][K] ----------------------------
__global__ void prep_weights(const float* __restrict__ W1, const float* __restrict__ W2) {
    int n = blockIdx.x, k = threadIdx.x, which = blockIdx.y;
    float v;
    __nv_bfloat16* dst;
    if (which == 0)      { v = W1[k * NF + n]; dst = g_WB1; }
    else if (which == 1) { v = W2[k * NF + n]; dst = g_WB2; }
    else if (which == 2) { v = W2[n * NF + k]; dst = g_WB2T; }
    else                 { v = W1[n * NF + k]; dst = g_WB1T; }
    dst[n * NF + k] = __float2bfloat16(v);
}

// ---- weight panel staging (K=64 slice of [256][256] bf16) -----------------
__device__ __forceinline__ void ldg_panel(const __nv_bfloat16* __restrict__ WB,
                                          int pan, int tid, uint4 r[8]) {
#pragma unroll
    for (int i = 0; i < 8; ++i) {
        int idx = tid + i * 256;
        int n = idx >> 3, c = idx & 7;
        r[i] = *reinterpret_cast<const uint4*>(
            (const char*)WB + n * (NF * 2) + pan * 128 + c * 16);
    }
}
__device__ __forceinline__ void sts_panel(uint32_t sb, int tid, const uint4 r[8]) {
#pragma unroll
    for (int i = 0; i < 8; ++i) {
        int idx = tid + i * 256;
        int n = idx >> 3, c = idx & 7;
        sts_128(sb + SMB_P + (uint32_t)(n * PSTRB + c * 16), r[i]);
    }
}

// ---- S (f32) -> X (bf16) conversion --------------------------------------
__device__ __forceinline__ void conv_S(uint32_t sb, int tid) {
    int r = tid >> 2, cq = tid & 3;
#pragma unroll
    for (int i = 0; i < 32; ++i) {
        int col = cq * 64 + i * 2;
        float v0 = lds_f32(sb + SMB_S + (uint32_t)((r * SSTR + col) * 4));
        float v1 = lds_f32(sb + SMB_S + (uint32_t)((r * SSTR + col + 1) * 4));
        sts_b32(sb + SMB_X + (uint32_t)(r * ASTRB + col * 2), pack_bf16x2(v0, v1));
    }
}

// ===========================================================================
// One fused GEMM (64 x 256 x 256) + epilogue.
// MODE 0: h1 = tanh(D+b1)            -> X
// MODE 1: g2 = wout*(1-tanh(D+b2)^2) -> Y
// MODE 2: g1 = D*(1-h1^2)  (h1 = X)  -> Y
// MODE 3: S update: n<128: p -= 0.05*D ; n>=128: q += 0.1*D
// MODE 4: S update: n<128 only (p), q untouched
// ===========================================================================
template <int MODE>
__device__ __forceinline__ void gemm(uint32_t sb, uint32_t aOffB,
                                     const __nv_bfloat16* __restrict__ WB, int tid) {
    const int w = tid >> 5, lane = tid & 31;
    const int n0 = w * 32;
    const int rr = lane & 7, grp = lane >> 3;       // grp 0..3
    // A lane base: matrix order (m0-7,k0-7),(m8-15,k0-7),(m0-7,k8-15),(m8-15,k8-15)
    const uint32_t aLane = sb + aOffB +
        (uint32_t)(((grp & 1) * 8 + rr) * ASTRB + ((grp >> 1) * 8) * 2);
    // B lane base (x2 uses lanes 0-15; use grp&1 for k-half)
    const uint32_t bLane = sb + SMB_P +
        (uint32_t)((n0 + rr) * PSTRB + (grp & 1) * 16);

    float acc[16][4];
#pragma unroll
    for (int i = 0; i < 16; ++i)
#pragma unroll
        for (int j = 0; j < 4; ++j) acc[i][j] = 0.0f;

    uint4 pr[8];
    ldg_panel(WB, 0, tid, pr);
#pragma unroll 1
    for (int pan = 0; pan < 4; ++pan) {
        __syncthreads();                 // prior panel reads / buffer writes done
        sts_panel(sb, tid, pr);
        __syncthreads();                 // panel visible
        if (pan < 3) ldg_panel(WB, pan + 1, tid, pr);   // overlap with MMAs
#pragma unroll
        for (int ks = 0; ks < 4; ++ks) {
            const uint32_t kaddA = (uint32_t)(pan * 128 + ks * 32);
            uint32_t a[4][4], b[4][2];
#pragma unroll
            for (int mt = 0; mt < 4; ++mt)
                ldm_x4(aLane + (uint32_t)(mt * 16 * ASTRB) + kaddA, a[mt]);
#pragma unroll
            for (int nt = 0; nt < 4; ++nt)
                ldm_x2(bLane + (uint32_t)(nt * 8 * PSTRB + ks * 32), b[nt]);
#pragma unroll
            for (int mt = 0; mt < 4; ++mt)
#pragma unroll
                for (int nt = 0; nt < 4; ++nt)
                    mma_bf16(acc[mt * 4 + nt], a[mt], b[nt]);
        }
    }
    __syncthreads();   // all warps done reading A/panel before epilogue writes

    const int qn = (lane & 3) * 2;     // n offset within 8-wide tile (even)
    const int qm = lane >> 2;          // m offset within 16-tall tile (0..7)
#pragma unroll
    for (int mt = 0; mt < 4; ++mt) {
#pragma unroll
        for (int nt = 0; nt < 4; ++nt) {
            const float* d = acc[mt * 4 + nt];
            const int n = n0 + nt * 8 + qn;
            const int m = mt * 16 + qm;
            if (MODE == 0 || MODE == 1) {
                const uint32_t bb = sb + ((MODE == 0) ? SMB_B1 : SMB_B2);
                float b0 = lds_f32(bb + (uint32_t)n * 4);
                float b1v = lds_f32(bb + (uint32_t)(n + 1) * 4);
                float h0 = fast_tanh(d[0] + b0), h1 = fast_tanh(d[1] + b1v);
                float h2 = fast_tanh(d[2] + b0), h3 = fast_tanh(d[3] + b1v);
                uint32_t lo, hi;
                if (MODE == 0) {
                    lo = pack_bf16x2(h0, h1); hi = pack_bf16x2(h2, h3);
                } else {
                    float w0 = lds_f32(sb + SMB_WO + (uint32_t)n * 4);
                    float w1 = lds_f32(sb + SMB_WO + (uint32_t)(n + 1) * 4);
                    lo = pack_bf16x2(w0 * (1.0f - h0 * h0), w1 * (1.0f - h1 * h1));
                    hi = pack_bf16x2(w0 * (1.0f - h2 * h2), w1 * (1.0f - h3 * h3));
                }
                const uint32_t dst = sb + ((MODE == 0) ? SMB_X : SMB_Y);
                sts_b32(dst + (uint32_t)(m * ASTRB + n * 2), lo);
                sts_b32(dst + (uint32_t)((m + 8) * ASTRB + n * 2), hi);
            } else if (MODE == 2) {
                float p0, p1, p2, p3;
                unpack_bf16x2(lds_b32(sb + SMB_X + (uint32_t)(m * ASTRB + n * 2)), p0, p1);
                unpack_bf16x2(lds_b32(sb + SMB_X + (uint32_t)((m + 8) * ASTRB + n * 2)), p2, p3);
                uint32_t lo = pack_bf16x2(d[0] * (1.0f - p0 * p0), d[1] * (1.0f - p1 * p1));
                uint32_t hi = pack_bf16x2(d[2] * (1.0f - p2 * p2), d[3] * (1.0f - p3 * p3));
                sts_b32(sb + SMB_Y + (uint32_t)(m * ASTRB + n * 2), lo);
                sts_b32(sb + SMB_Y + (uint32_t)((m + 8) * ASTRB + n * 2), hi);
            } else {
                if (MODE == 4 && n >= 128) continue;
#pragma unroll
                for (int e = 0; e < 4; ++e) {
                    const int ni = n + (e & 1);
                    const int mi = m + (e >> 1) * 8;
                    int col; float coef;
                    if (ni < 128) { col = 128 + ni; coef = -0.05f; }   // p -= 0.05*dHq
                    else          { col = ni - 128; coef = 0.1f;   }   // q += 0.1*dHp
                    const uint32_t a2 = sb + SMB_S + (uint32_t)((mi * SSTR + col) * 4);
                    sts_f32(a2, lds_f32(a2) + coef * d[e]);
                }
            }
        }
    }
    __syncthreads();   // epilogue results visible to everyone
}

// ---------------------------------------------------------------------------
__global__ void __launch_bounds__(256, 1) leap_kernel(
    const float* __restrict__ x,
    const float* __restrict__ b1, const float* __restrict__ b2,
    const float* __restrict__ wout,
    float* __restrict__ out) {
    extern __shared__ char smem[];
    const uint32_t sb = smem_u32(smem);
    float* smf = reinterpret_cast<float*>(smem);
    const int tid = threadIdx.x;
    const int rowBase = blockIdx.x * MR;

    // stage biases + wout (256 each)
    sts_f32(sb + SMB_B1 + (uint32_t)tid * 4, b1[tid]);
    sts_f32(sb + SMB_B2 + (uint32_t)tid * 4, b2[tid]);
    sts_f32(sb + SMB_WO + (uint32_t)tid * 4, wout[tid]);

    // load x -> S: q = x[b,15,:], p = q - x[b,14,:]
    {
        const float4* x4 = reinterpret_cast<const float4*>(x);
#pragma unroll
        for (int it = 0; it < 8; ++it) {
            int f4 = tid + it * 256;       // 0..2047
            int row = f4 >> 5;             // 0..63
            int fc = f4 & 31;              // float4 idx in 128 floats
            long b = rowBase + row;
            float4 q  = x4[(b * 16 + 15) * 32 + fc];
            float4 xm = x4[(b * 16 + 14) * 32 + fc];
            float4 p = make_float4(q.x - xm.x, q.y - xm.y, q.z - xm.z, q.w - xm.w);
            *reinterpret_cast<float4*>(smf + row * SSTR + fc * 4) = q;
            *reinterpret_cast<float4*>(smf + row * SSTR + 128 + fc * 4) = p;
        }
    }
    __syncthreads();

#pragma unroll 1
    for (int s = 0; s < 3; ++s) {
        // eval 1: full leapfrog update
        conv_S(sb, tid);
        gemm<0>(sb, SMB_X, g_WB1,  tid);
        gemm<1>(sb, SMB_X, g_WB2,  tid);
        gemm<2>(sb, SMB_Y, g_WB2T, tid);
        gemm<3>(sb, SMB_Y, g_WB1T, tid);
        // eval 2: p-only update
        conv_S(sb, tid);
        gemm<0>(sb, SMB_X, g_WB1,  tid);
        gemm<1>(sb, SMB_X, g_WB2,  tid);
        gemm<2>(sb, SMB_Y, g_WB2T, tid);
        gemm<4>(sb, SMB_Y, g_WB1T, tid);
    }

    // write out
#pragma unroll
    for (int it = 0; it < 16; ++it) {
        int f4 = tid + it * 256;           // 0..4095
        int row = f4 >> 6;
        int fc = f4 & 63;
        long b = rowBase + row;
        float4 v = *reinterpret_cast<const float4*>(smf + row * SSTR + fc * 4);
        reinterpret_cast<float4*>(out)[b * 64 + fc] = v;
    }
}

// ---------------------------------------------------------------------------
extern "C" void kernel_launch(void* const* d_in, const int* in_sizes, int n_in,
                              void* d_out, int out_size) {
    const float* x    = (const float*)d_in[0];
    const float* W1   = (const float*)d_in[1];
    const float* b1   = (const float*)d_in[2];
    const float* W2   = (const float*)d_in[3];
    const float* b2   = (const float*)d_in[4];
    const float* Wout = (const float*)d_in[5];
    float* out = (float*)d_out;

    prep_weights<<<dim3(NF, 4), NF>>>(W1, W2);

    cudaFuncSetAttribute(leap_kernel,
                         cudaFuncAttributeMaxDynamicSharedMemorySize, SMEM_TOTAL);
    leap_kernel<<<1024, 256, SMEM_TOTAL>>>(x, b1, b2, Wout, out);
}

// round 15
// speedup vs baseline: 5.6199x; 1.3318x over previous
#include <cuda_runtime.h>
#include <cuda_bf16.h>
#include <cstdint>

// ===========================================================================
// SymplecticLeapfrogLayer via mma.sync bf16, round 15:
//  - B operand now read DIRECTLY from global memory in a pre-packed
//    fragment-ordered layout (one uint2 = {b0,b1} mma fragment per thread
//    per (ks,nt)) -> removes panel STS + B ldmatrix + ALL k-loop barriers.
//  - MODE 4 (final N=128 GEMM): warps 4-7 skip the k-loop.
// One CTA = 64 batch rows, 8 warps, warp owns 32 N-columns x all 64 M rows.
// A (bf16 activations) in SMEM via ldmatrix.x4. S=[q|p] f32 in SMEM.
// ===========================================================================

#define NF 256
#define MR 64
#define SSTR 260      // S f32 row stride (floats)
#define ASTRB 528     // X/Y bf16 row stride in BYTES

// ---- SMEM byte offsets ----------------------------------------------------
#define SMB_S  0
#define SMB_X  (MR * SSTR * 4)            // 66560
#define SMB_Y  (SMB_X + MR * ASTRB)       // 100352
#define SMB_B1 (SMB_Y + MR * ASTRB)       // 134144
#define SMB_B2 (SMB_B1 + 1024)
#define SMB_WO (SMB_B2 + 1024)
#define SMEM_TOTAL (SMB_WO + 1024)        // 137216 B

// Packed weights: g_WP[which][(ks*256 + n)*4 + j] = uint2{ pack(B[n][ks*16+2j],
// B[n][ks*16+2j+1]), pack(B[n][ks*16+8+2j], B[n][ks*16+8+2j+1]) }
// where B[n][k] is the K-major operand of GEMM 'which'.
__device__ uint2 g_WP[4][16 * 256 * 4];

// ---- helpers --------------------------------------------------------------
__device__ __forceinline__ uint32_t smem_u32(const void* p) {
    uint32_t a;
    asm("{ .reg .u64 t; cvta.to.shared.u64 t, %1; cvt.u32.u64 %0, t; }"
        : "=r"(a) : "l"(p));
    return a;
}
__device__ __forceinline__ float lds_f32(uint32_t a) {
    float v; asm volatile("ld.shared.f32 %0, [%1];" : "=f"(v) : "r"(a)); return v;
}
__device__ __forceinline__ void sts_f32(uint32_t a, float v) {
    asm volatile("st.shared.f32 [%0], %1;" :: "r"(a), "f"(v) : "memory");
}
__device__ __forceinline__ uint32_t lds_b32(uint32_t a) {
    uint32_t v; asm volatile("ld.shared.b32 %0, [%1];" : "=r"(v) : "r"(a)); return v;
}
__device__ __forceinline__ void sts_b32(uint32_t a, uint32_t v) {
    asm volatile("st.shared.b32 [%0], %1;" :: "r"(a), "r"(v) : "memory");
}
__device__ __forceinline__ float fast_tanh(float x) {
    float r; asm("tanh.approx.f32 %0, %1;" : "=f"(r) : "f"(x)); return r;
}
__device__ __forceinline__ uint32_t pack_bf16x2(float lo, float hi) {
    uint32_t r;
    asm("cvt.rn.bf16x2.f32 %0, %1, %2;" : "=r"(r) : "f"(hi), "f"(lo));
    return r;
}
__device__ __forceinline__ void unpack_bf16x2(uint32_t v, float& f0, float& f1) {
    __nv_bfloat162 h = *reinterpret_cast<__nv_bfloat162*>(&v);
    f0 = __bfloat162float(h.x); f1 = __bfloat162float(h.y);
}
__device__ __forceinline__ void ldm_x4(uint32_t a, uint32_t r[4]) {
    asm volatile("ldmatrix.sync.aligned.m8n8.x4.shared.b16 {%0,%1,%2,%3}, [%4];"
                 : "=r"(r[0]), "=r"(r[1]), "=r"(r[2]), "=r"(r[3]) : "r"(a));
}
__device__ __forceinline__ void mma_bf16(float d[4], const uint32_t a[4], const uint32_t b[2]) {
    asm volatile(
        "mma.sync.aligned.m16n8k16.row.col.f32.bf16.bf16.f32 "
        "{%0,%1,%2,%3},{%4,%5,%6,%7},{%8,%9},{%0,%1,%2,%3};"
        : "+f"(d[0]), "+f"(d[1]), "+f"(d[2]), "+f"(d[3])
        : "r"(a[0]), "r"(a[1]), "r"(a[2]), "r"(a[3]), "r"(b[0]), "r"(b[1]));
}

// ---- weight prep: fp32 -> packed bf16 mma fragments -----------------------
// which 0: B[n][k]=W1[k][n]   (h1 = S @ W1)
// which 1: B[n][k]=W2[k][n]   (h2 = h1 @ W2)
// which 2: B[n][k]=W2[n][k]   (g1 = g2 @ W2^T)
// which 3: B[n][k]=W1[n][k]   (dH = g1 @ W1^T)
__global__ void prep_weights(const float* __restrict__ W1, const float* __restrict__ W2) {
    int n = blockIdx.x, which = blockIdx.y;
    int t = threadIdx.x;            // 64 threads: ks(16) x j(4)
    int ks = t >> 2, j = t & 3;
    int k0 = ks * 16 + 2 * j;

    const float* src = (which == 0 || which == 3) ? W1 : W2;
    bool kmaj = (which < 2);        // element at (k,n) = src[k*256+n] else src[n*256+k]
    float s00, s01, s10, s11;
    if (kmaj) {
        s00 = src[k0 * NF + n];       s01 = src[(k0 + 1) * NF + n];
        s10 = src[(k0 + 8) * NF + n]; s11 = src[(k0 + 9) * NF + n];
    } else {
        s00 = src[n * NF + k0];       s01 = src[n * NF + k0 + 1];
        s10 = src[n * NF + k0 + 8];   s11 = src[n * NF + k0 + 9];
    }
    uint2 v;
    v.x = pack_bf16x2(s00, s01);
    v.y = pack_bf16x2(s10, s11);
    g_WP[which][(ks * NF + n) * 4 + j] = v;
}

// ---- S (f32) -> X (bf16) conversion --------------------------------------
__device__ __forceinline__ void conv_S(uint32_t sb, int tid) {
    int r = tid >> 2, cq = tid & 3;
#pragma unroll
    for (int i = 0; i < 32; ++i) {
        int col = cq * 64 + i * 2;
        float v0 = lds_f32(sb + SMB_S + (uint32_t)((r * SSTR + col) * 4));
        float v1 = lds_f32(sb + SMB_S + (uint32_t)((r * SSTR + col + 1) * 4));
        sts_b32(sb + SMB_X + (uint32_t)(r * ASTRB + col * 2), pack_bf16x2(v0, v1));
    }
    __syncthreads();   // X ready before gemm<0> reads it
}

// ===========================================================================
// One fused GEMM (64 x 256 x 256) + epilogue. B streams from g_WP (L2).
// MODE 0: h1 = tanh(D+b1)            -> X
// MODE 1: g2 = wout*(1-tanh(D+b2)^2) -> Y
// MODE 2: g1 = D*(1-h1^2)  (h1 = X)  -> Y
// MODE 3: S update: n<128: p -= 0.05*D ; n>=128: q += 0.1*D
// MODE 4: S update: n<128 only; warps 4-7 skip the k-loop entirely
// ===========================================================================
template <int MODE>
__device__ __forceinline__ void gemm(uint32_t sb, uint32_t aOffB,
                                     const uint2* __restrict__ Wp, int tid) {
    const int w = tid >> 5, lane = tid & 31;
    const int n0 = w * 32;
    const int rr = lane & 7, grp = lane >> 3;
    // A lane base: matrices (m0-7,k0-7),(m8-15,k0-7),(m0-7,k8-15),(m8-15,k8-15)
    const uint32_t aLane = sb + aOffB +
        (uint32_t)(((grp & 1) * 8 + rr) * ASTRB + ((grp >> 1) * 8) * 2);
    // B fragment pointer: element (ks,nt) at + ks*1024 + nt*32
    const uint2* bPtr = Wp + (uint32_t)((n0 + (lane >> 2)) * 4 + (lane & 3));

    float acc[16][4];
#pragma unroll
    for (int i = 0; i < 16; ++i)
#pragma unroll
        for (int j = 0; j < 4; ++j) acc[i][j] = 0.0f;

    if (MODE != 4 || w < 4) {
#pragma unroll 4
        for (int ks = 0; ks < 16; ++ks) {
            uint32_t a[4][4];
            uint2 bv[4];
#pragma unroll
            for (int nt = 0; nt < 4; ++nt)
                bv[nt] = __ldg(bPtr + ks * 1024 + nt * 32);
#pragma unroll
            for (int mt = 0; mt < 4; ++mt)
                ldm_x4(aLane + (uint32_t)(mt * 16 * ASTRB + ks * 32), a[mt]);
#pragma unroll
            for (int mt = 0; mt < 4; ++mt)
#pragma unroll
                for (int nt = 0; nt < 4; ++nt)
                    mma_bf16(acc[mt * 4 + nt], a[mt],
                             reinterpret_cast<const uint32_t*>(&bv[nt]));
        }
    }
    __syncthreads();   // all warps done reading A before epilogue overwrites X/Y

    const int qn = (lane & 3) * 2;
    const int qm = lane >> 2;
#pragma unroll
    for (int mt = 0; mt < 4; ++mt) {
#pragma unroll
        for (int nt = 0; nt < 4; ++nt) {
            const float* d = acc[mt * 4 + nt];
            const int n = n0 + nt * 8 + qn;
            const int m = mt * 16 + qm;
            if (MODE == 0 || MODE == 1) {
                const uint32_t bb = sb + ((MODE == 0) ? SMB_B1 : SMB_B2);
                float b0 = lds_f32(bb + (uint32_t)n * 4);
                float b1v = lds_f32(bb + (uint32_t)(n + 1) * 4);
                float h0 = fast_tanh(d[0] + b0), h1 = fast_tanh(d[1] + b1v);
                float h2 = fast_tanh(d[2] + b0), h3 = fast_tanh(d[3] + b1v);
                uint32_t lo, hi;
                if (MODE == 0) {
                    lo = pack_bf16x2(h0, h1); hi = pack_bf16x2(h2, h3);
                } else {
                    float w0 = lds_f32(sb + SMB_WO + (uint32_t)n * 4);
                    float w1 = lds_f32(sb + SMB_WO + (uint32_t)(n + 1) * 4);
                    lo = pack_bf16x2(w0 * (1.0f - h0 * h0), w1 * (1.0f - h1 * h1));
                    hi = pack_bf16x2(w0 * (1.0f - h2 * h2), w1 * (1.0f - h3 * h3));
                }
                const uint32_t dst = sb + ((MODE == 0) ? SMB_X : SMB_Y);
                sts_b32(dst + (uint32_t)(m * ASTRB + n * 2), lo);
                sts_b32(dst + (uint32_t)((m + 8) * ASTRB + n * 2), hi);
            } else if (MODE == 2) {
                float p0, p1, p2, p3;
                unpack_bf16x2(lds_b32(sb + SMB_X + (uint32_t)(m * ASTRB + n * 2)), p0, p1);
                unpack_bf16x2(lds_b32(sb + SMB_X + (uint32_t)((m + 8) * ASTRB + n * 2)), p2, p3);
                uint32_t lo = pack_bf16x2(d[0] * (1.0f - p0 * p0), d[1] * (1.0f - p1 * p1));
                uint32_t hi = pack_bf16x2(d[2] * (1.0f - p2 * p2), d[3] * (1.0f - p3 * p3));
                sts_b32(sb + SMB_Y + (uint32_t)(m * ASTRB + n * 2), lo);
                sts_b32(sb + SMB_Y + (uint32_t)((m + 8) * ASTRB + n * 2), hi);
            } else {
                if (MODE == 4 && n >= 128) continue;
#pragma unroll
                for (int e = 0; e < 4; ++e) {
                    const int ni = n + (e & 1);
                    const int mi = m + (e >> 1) * 8;
                    int col; float coef;
                    if (ni < 128) { col = 128 + ni; coef = -0.05f; }   // p -= 0.05*dHq
                    else          { col = ni - 128; coef = 0.1f;   }   // q += 0.1*dHp
                    const uint32_t a2 = sb + SMB_S + (uint32_t)((mi * SSTR + col) * 4);
                    sts_f32(a2, lds_f32(a2) + coef * d[e]);
                }
            }
        }
    }
    __syncthreads();   // epilogue results visible before next GEMM reads them
}

// ---------------------------------------------------------------------------
__global__ void __launch_bounds__(256, 1) leap_kernel(
    const float* __restrict__ x,
    const float* __restrict__ b1, const float* __restrict__ b2,
    const float* __restrict__ wout,
    float* __restrict__ out) {
    extern __shared__ char smem[];
    const uint32_t sb = smem_u32(smem);
    float* smf = reinterpret_cast<float*>(smem);
    const int tid = threadIdx.x;
    const int rowBase = blockIdx.x * MR;

    sts_f32(sb + SMB_B1 + (uint32_t)tid * 4, b1[tid]);
    sts_f32(sb + SMB_B2 + (uint32_t)tid * 4, b2[tid]);
    sts_f32(sb + SMB_WO + (uint32_t)tid * 4, wout[tid]);

    // load x -> S: q = x[b,15,:], p = q - x[b,14,:]
    {
        const float4* x4 = reinterpret_cast<const float4*>(x);
#pragma unroll
        for (int it = 0; it < 8; ++it) {
            int f4 = tid + it * 256;
            int row = f4 >> 5;
            int fc = f4 & 31;
            long b = rowBase + row;
            float4 q  = x4[(b * 16 + 15) * 32 + fc];
            float4 xm = x4[(b * 16 + 14) * 32 + fc];
            float4 p = make_float4(q.x - xm.x, q.y - xm.y, q.z - xm.z, q.w - xm.w);
            *reinterpret_cast<float4*>(smf + row * SSTR + fc * 4) = q;
            *reinterpret_cast<float4*>(smf + row * SSTR + 128 + fc * 4) = p;
        }
    }
    __syncthreads();

#pragma unroll 1
    for (int s = 0; s < 3; ++s) {
        // eval 1: full leapfrog update
        conv_S(sb, tid);
        gemm<0>(sb, SMB_X, g_WP[0], tid);
        gemm<1>(sb, SMB_X, g_WP[1], tid);
        gemm<2>(sb, SMB_Y, g_WP[2], tid);
        gemm<3>(sb, SMB_Y, g_WP[3], tid);
        // eval 2: p-only update
        conv_S(sb, tid);
        gemm<0>(sb, SMB_X, g_WP[0], tid);
        gemm<1>(sb, SMB_X, g_WP[1], tid);
        gemm<2>(sb, SMB_Y, g_WP[2], tid);
        gemm<4>(sb, SMB_Y, g_WP[3], tid);
    }

    // write out
#pragma unroll
    for (int it = 0; it < 16; ++it) {
        int f4 = tid + it * 256;
        int row = f4 >> 6;
        int fc = f4 & 63;
        long b = rowBase + row;
        float4 v = *reinterpret_cast<const float4*>(smf + row * SSTR + fc * 4);
        reinterpret_cast<float4*>(out)[b * 64 + fc] = v;
    }
}

// ---------------------------------------------------------------------------
extern "C" void kernel_launch(void* const* d_in, const int* in_sizes, int n_in,
                              void* d_out, int out_size) {
    const float* x    = (const float*)d_in[0];
    const float* W1   = (const float*)d_in[1];
    const float* b1   = (const float*)d_in[2];
    const float* W2   = (const float*)d_in[3];
    const float* b2   = (const float*)d_in[4];
    const float* Wout = (const float*)d_in[5];
    float* out = (float*)d_out;

    prep_weights<<<dim3(NF, 4), 64>>>(W1, W2);

    cudaFuncSetAttribute(leap_kernel,
                         cudaFuncAttributeMaxDynamicSharedMemorySize, SMEM_TOTAL);
    leap_kernel<<<1024, 256, SMEM_TOTAL>>>(x, b1, b2, Wout, out);
}